// round 9
// baseline (speedup 1.0000x reference)
#include <cuda_runtime.h>
#include <cuda_fp16.h>
#include <cstdint>

#define VOCAB 14
#define EMBED 10
#define HID   50
#define HP    64          // padded unit slots (cached-k + gate-init tables)
#define KC    12          // k's cached in registers as fp32 (96 regs)
#define KS    (HID - KC)  // streamed k's (fp16)
#define SROWF 56          // sH row stride in floats
#define TLEN  2048
#define NBATCH 4096
#define ROWS  2           // batch rows per warp

typedef unsigned long long ull;

// gWk[k][u] (fp32, padded u<64): (0.5*Wi, 0.5*Wf, Wg, 0.5*Wo) — k<KC reg-cached
// gWH[(k-KC)*32 + lane]: uint4 of 8 halves {i,f,g,o}(u1=lane), {i,f,g,o}(u2=lane+32)
// gXT[v][u] (fp32): per-token gate init, same scaling
__device__ float4 gWk[HID * HP];
__device__ __align__(16) __half gWH[KS * 32 * 8];
__device__ float4 gXT[VOCAB * HP];
__device__ float  gq[HID];
__device__ float  gc0;

// ---------------------------------------------------------------------------
__global__ void prep_kernel(const float* __restrict__ emb,
                            const float* __restrict__ W_ih,
                            const float* __restrict__ W_hh,
                            const float* __restrict__ b_ih,
                            const float* __restrict__ b_hh,
                            const float* __restrict__ W1,
                            const float* __restrict__ b1,
                            const float* __restrict__ W2,
                            const float* __restrict__ b2)
{
    int tid = threadIdx.x;

    for (int i = tid; i < HID * HP; i += blockDim.x) {
        int k = i / HP, u = i % HP;
        float4 w = make_float4(0.f, 0.f, 0.f, 0.f);
        if (u < HID) {
            w.x = 0.5f * W_hh[(0 * HID + u) * HID + k];
            w.y = 0.5f * W_hh[(1 * HID + u) * HID + k];
            w.z =        W_hh[(2 * HID + u) * HID + k];
            w.w = 0.5f * W_hh[(3 * HID + u) * HID + k];
        }
        gWk[i] = w;
    }

    // fp16 streamed table: per (k, lane) 8 halves = u1{i,f,g,o}, u2{i,f,g,o}
    for (int i = tid; i < KS * 32; i += blockDim.x) {
        int k = KC + i / 32, L = i % 32;
        __half* p = gWH + i * 8;
        int u1 = L, u2 = L + 32;
        #pragma unroll
        for (int g = 0; g < 4; g++) {
            float s = (g == 2) ? 1.0f : 0.5f;
            p[g] = __float2half_rn(s * W_hh[(g * HID + u1) * HID + k]);
            p[4 + g] = (u2 < HID)
                ? __float2half_rn(s * W_hh[(g * HID + u2) * HID + k])
                : __float2half_rn(0.0f);
        }
    }

    for (int i = tid; i < VOCAB * HP; i += blockDim.x) {
        int v = i / HP, u = i % HP;
        float4 x = make_float4(0.f, 0.f, 0.f, 0.f);
        if (u < HID) {
            float* px = reinterpret_cast<float*>(&x);
            #pragma unroll
            for (int g = 0; g < 4; g++) {
                int c = g * HID + u;
                float s = b_ih[c] + b_hh[c];
                #pragma unroll
                for (int e = 0; e < EMBED; e++)
                    s += emb[v * EMBED + e] * W_ih[c * EMBED + e];
                px[g] = (g == 2) ? s : 0.5f * s;
            }
        }
        gXT[i] = x;
    }

    for (int u = tid; u < HID; u += blockDim.x) {
        float s = 0.f;
        for (int m = 0; m < HID; m++) s += W2[m] * W1[m * HID + u];
        gq[u] = s;
    }
    if (tid == 0) {
        float s = b2[0];
        for (int m = 0; m < HID; m++) s += W2[m] * b1[m];
        gc0 = s;
    }
}

// ---------------------------------------------------------------------------
__device__ __forceinline__ ull ffma2(ull a, ull b, ull c) {
    ull d;
    asm("fma.rn.f32x2 %0, %1, %2, %3;" : "=l"(d) : "l"(a), "l"(b), "l"(c));
    return d;
}
__device__ __forceinline__ ull pk2(float x, float y) {
    ull d;
    asm("mov.b64 %0, {%1, %2};" : "=l"(d) : "f"(x), "f"(y));
    return d;
}
__device__ __forceinline__ ull cvt2(unsigned v) {      // half2 bits -> packed f32x2
    __half2 h = *reinterpret_cast<__half2*>(&v);
    float2 f = __half22float2(h);
    return pk2(f.x, f.y);
}
__device__ __forceinline__ ull dup_(float x) {         // (x,x) packed f32x2
    ull d;
    asm("mov.b64 %0, {%1, %1};" : "=l"(d) : "f"(x));
    return d;
}
__device__ __forceinline__ float lo_(ull v) { return __uint_as_float((unsigned)v); }
__device__ __forceinline__ float hi_(ull v) { return __uint_as_float((unsigned)(v >> 32)); }

__device__ __forceinline__ float tanhfast(float x) {
    float y;
    asm("tanh.approx.f32 %0, %1;" : "=f"(y) : "f"(x));
    return y;
}
// gate pre-scaled by 0.5: sigma(2y) = 0.5*tanh(y)+0.5
__device__ __forceinline__ float sigp(float y) { return fmaf(0.5f, tanhfast(y), 0.5f); }

// one k-pair of FFMA2 for all rows, given weight pairs and h-dups
#define KPAIR(W0if, W0go, W1if, W1go, V0if, V0go, V1if, V1go, HA, HB)          \
    _Pragma("unroll")                                                          \
    for (int j = 0; j < ROWS; j++) {                                           \
        a1if[j] = ffma2(W0if, HA[j], a1if[j]);                                 \
        a1go[j] = ffma2(W0go, HA[j], a1go[j]);                                 \
        a2if[j] = ffma2(W1if, HA[j], a2if[j]);                                 \
        a2go[j] = ffma2(W1go, HA[j], a2go[j]);                                 \
        a1if[j] = ffma2(V0if, HB[j], a1if[j]);                                 \
        a1go[j] = ffma2(V0go, HB[j], a1go[j]);                                 \
        a2if[j] = ffma2(V1if, HB[j], a2if[j]);                                 \
        a2go[j] = ffma2(V1go, HB[j], a2go[j]);                                 \
    }

// ---------------------------------------------------------------------------
// 1 warp per CTA, 2 batch rows, warp-autonomous recurrence. 2048 warps total
// (~13.8/SM, 3.46/SMSP) for latency hiding; fp16 streamed weights keep the
// per-warp L1 stream low enough that doubling warp count stays under the wall.
// Lane L owns units {L, L+32}; f32x2 packs (i,f) and (g,o).
// ---------------------------------------------------------------------------
__global__ __launch_bounds__(32) void lstm_kernel(const int* __restrict__ tokens,
                                                  float* __restrict__ out)
{
    __shared__ __align__(16) float sH[ROWS][SROWF];

    const int lane = threadIdx.x;
    const int b0   = blockIdx.x * ROWS;
    const int u1   = lane;
    const int u2   = lane + 32;
    const bool live2 = (u2 < HID);

    for (int i = lane; i < ROWS * SROWF; i += 32)
        (&sH[0][0])[i] = 0.f;
    __syncwarp();

    float c1[ROWS], c2[ROWS];
    #pragma unroll
    for (int j = 0; j < ROWS; j++) { c1[j] = 0.f; c2[j] = 0.f; }

    // register-cached fp32 weights for k = 0..KC-1
    ull cw[KC * 4];
    #pragma unroll
    for (int k = 0; k < KC; k++) {
        ulonglong2 a = __ldg(reinterpret_cast<const ulonglong2*>(gWk + k * HP + u1));
        ulonglong2 b = __ldg(reinterpret_cast<const ulonglong2*>(gWk + k * HP + u2));
        cw[k * 4 + 0] = a.x;  cw[k * 4 + 1] = a.y;
        cw[k * 4 + 2] = b.x;  cw[k * 4 + 3] = b.y;
    }

    const float4* __restrict__ Xp = gXT;
    const uint4*  __restrict__ Hp = reinterpret_cast<const uint4*>(gWH);

    const int* tp[ROWS];
    int tk[ROWS];
    #pragma unroll
    for (int j = 0; j < ROWS; j++) {
        tp[j] = tokens + (size_t)(b0 + j) * TLEN;
        tk[j] = __ldg(tp[j]);
    }

    for (int t = 0; t < TLEN; ++t) {
        const int t2 = (t + 1 < TLEN) ? t + 1 : t;
        int tkn[ROWS];
        #pragma unroll
        for (int j = 0; j < ROWS; j++) tkn[j] = __ldg(tp[j] + t2);

        // accumulators init from token gate-init table
        ull a1if[ROWS], a1go[ROWS], a2if[ROWS], a2go[ROWS];
        #pragma unroll
        for (int j = 0; j < ROWS; j++) {
            ulonglong2 v0 = __ldg(reinterpret_cast<const ulonglong2*>(Xp + tk[j] * HP + u1));
            ulonglong2 v1 = __ldg(reinterpret_cast<const ulonglong2*>(Xp + tk[j] * HP + u2));
            a1if[j] = v0.x;  a1go[j] = v0.y;
            a2if[j] = v1.x;  a2go[j] = v1.y;
        }

        // ---- cached k's (0..KC-1), groups of 4: 1 LDS.128 per row per group
        #pragma unroll
        for (int kg = 0; kg < KC; kg += 4) {
            float4 hv[ROWS];
            ull hA[ROWS], hB[ROWS], hC[ROWS], hD[ROWS];
            #pragma unroll
            for (int j = 0; j < ROWS; j++) {
                hv[j] = *reinterpret_cast<const float4*>(&sH[j][kg]);
                hA[j] = dup_(hv[j].x);  hB[j] = dup_(hv[j].y);
                hC[j] = dup_(hv[j].z);  hD[j] = dup_(hv[j].w);
            }
            KPAIR(cw[kg*4+0], cw[kg*4+1], cw[kg*4+2], cw[kg*4+3],
                  cw[kg*4+4], cw[kg*4+5], cw[kg*4+6], cw[kg*4+7], hA, hB)
            KPAIR(cw[kg*4+8], cw[kg*4+9], cw[kg*4+10], cw[kg*4+11],
                  cw[kg*4+12], cw[kg*4+13], cw[kg*4+14], cw[kg*4+15], hC, hD)
        }

        // ---- streamed k's (KC..47), groups of 4: fp16, one LDG.128 per k
        #pragma unroll
        for (int kg = KC; kg < 48; kg += 4) {
            uint4 w0 = __ldg(Hp + (kg + 0 - KC) * 32 + lane);
            uint4 w1 = __ldg(Hp + (kg + 1 - KC) * 32 + lane);
            uint4 w2 = __ldg(Hp + (kg + 2 - KC) * 32 + lane);
            uint4 w3 = __ldg(Hp + (kg + 3 - KC) * 32 + lane);
            float4 hv[ROWS];
            ull hA[ROWS], hB[ROWS], hC[ROWS], hD[ROWS];
            #pragma unroll
            for (int j = 0; j < ROWS; j++) {
                hv[j] = *reinterpret_cast<const float4*>(&sH[j][kg]);
                hA[j] = dup_(hv[j].x);  hB[j] = dup_(hv[j].y);
                hC[j] = dup_(hv[j].z);  hD[j] = dup_(hv[j].w);
            }
            KPAIR(cvt2(w0.x), cvt2(w0.y), cvt2(w0.z), cvt2(w0.w),
                  cvt2(w1.x), cvt2(w1.y), cvt2(w1.z), cvt2(w1.w), hA, hB)
            KPAIR(cvt2(w2.x), cvt2(w2.y), cvt2(w2.z), cvt2(w2.w),
                  cvt2(w3.x), cvt2(w3.y), cvt2(w3.z), cvt2(w3.w), hC, hD)
        }

        // ---- final pair k = 48, 49
        {
            uint4 w0 = __ldg(Hp + (48 - KC) * 32 + lane);
            uint4 w1 = __ldg(Hp + (49 - KC) * 32 + lane);
            ull hA[ROWS], hB[ROWS];
            #pragma unroll
            for (int j = 0; j < ROWS; j++) {
                float2 hv = *reinterpret_cast<const float2*>(&sH[j][48]);
                hA[j] = dup_(hv.x);  hB[j] = dup_(hv.y);
            }
            KPAIR(cvt2(w0.x), cvt2(w0.y), cvt2(w0.z), cvt2(w0.w),
                  cvt2(w1.x), cvt2(w1.y), cvt2(w1.z), cvt2(w1.w), hA, hB)
        }

        __syncwarp();

        #pragma unroll
        for (int j = 0; j < ROWS; j++) {
            const bool live = (tk[j] != 0);
            {   // unit u1
                float i = sigp(lo_(a1if[j]));
                float f = sigp(hi_(a1if[j]));
                float g = tanhfast(lo_(a1go[j]));
                float o = sigp(hi_(a1go[j]));
                float cn = fmaf(f, c1[j], i * g);
                float hn = o * tanhfast(cn);
                if (live) { c1[j] = cn; sH[j][u1] = hn; }
            }
            if (live2) {   // unit u2
                float i = sigp(lo_(a2if[j]));
                float f = sigp(hi_(a2if[j]));
                float g = tanhfast(lo_(a2go[j]));
                float o = sigp(hi_(a2go[j]));
                float cn = fmaf(f, c2[j], i * g);
                float hn = o * tanhfast(cn);
                if (live) { c2[j] = cn; sH[j][u2] = hn; }
            }
        }
        __syncwarp();

        #pragma unroll
        for (int j = 0; j < ROWS; j++) tk[j] = tkn[j];
    }

    // collapsed MLP head: out = sigmoid(c0 + q . h_final)   (accurate sigmoid)
    if (lane < ROWS) {
        const int j = lane;
        float s = gc0;
        #pragma unroll 10
        for (int k = 0; k < HID; k++) s += gq[k] * sH[j][k];
        out[b0 + j] = 1.0f / (1.0f + __expf(-s));
    }
}

// ---------------------------------------------------------------------------
extern "C" void kernel_launch(void* const* d_in, const int* in_sizes, int n_in,
                              void* d_out, int out_size)
{
    const int*   tokens = (const int*)  d_in[0];
    const float* emb    = (const float*)d_in[1];
    const float* W_ih   = (const float*)d_in[2];
    const float* W_hh   = (const float*)d_in[3];
    const float* b_ih   = (const float*)d_in[4];
    const float* b_hh   = (const float*)d_in[5];
    const float* W1     = (const float*)d_in[6];
    const float* b1     = (const float*)d_in[7];
    const float* W2     = (const float*)d_in[8];
    const float* b2     = (const float*)d_in[9];
    float* out = (float*)d_out;

    prep_kernel<<<1, 256>>>(emb, W_ih, W_hh, b_ih, b_hh, W1, b1, W2, b2);
    lstm_kernel<<<NBATCH / ROWS, 32>>>(tokens, out);
}

// round 10
// speedup vs baseline: 1.4465x; 1.4465x over previous
#include <cuda_runtime.h>
#include <cstdint>

#define VOCAB 14
#define EMBED 10
#define HID   50
#define UW    25          // units per warp
#define KC    20          // k's cached in registers (80 regs)
#define SROWF 52          // sH row stride in floats
#define TLEN  2048
#define NBATCH 4096
#define ROWS  4           // batch rows per CTA (shared by both warps)

typedef unsigned long long ull;

// gW2[k*64 + w*32 + lane] = (0.5*Wi, 0.5*Wf, Wg, 0.5*Wo) for unit u = w*25+lane (lane<25; else 0)
// gX2[v*64 + w*32 + lane] = per-token gate init for unit u, same scaling
__device__ float4 gW2[HID * 64];
__device__ float4 gX2[VOCAB * 64];
__device__ float  gq[HID];
__device__ float  gc0;

// ---------------------------------------------------------------------------
__global__ void prep_kernel(const float* __restrict__ emb,
                            const float* __restrict__ W_ih,
                            const float* __restrict__ W_hh,
                            const float* __restrict__ b_ih,
                            const float* __restrict__ b_hh,
                            const float* __restrict__ W1,
                            const float* __restrict__ b1,
                            const float* __restrict__ W2,
                            const float* __restrict__ b2)
{
    int tid = threadIdx.x;

    for (int i = tid; i < HID * 64; i += blockDim.x) {
        int k = i / 64, s = i % 64;
        int w = s >> 5, L = s & 31;
        int u = w * UW + L;
        float4 v = make_float4(0.f, 0.f, 0.f, 0.f);
        if (L < UW && u < HID) {
            v.x = 0.5f * W_hh[(0 * HID + u) * HID + k];
            v.y = 0.5f * W_hh[(1 * HID + u) * HID + k];
            v.z =        W_hh[(2 * HID + u) * HID + k];
            v.w = 0.5f * W_hh[(3 * HID + u) * HID + k];
        }
        gW2[i] = v;
    }

    for (int i = tid; i < VOCAB * 64; i += blockDim.x) {
        int v = i / 64, s = i % 64;
        int w = s >> 5, L = s & 31;
        int u = w * UW + L;
        float4 x = make_float4(0.f, 0.f, 0.f, 0.f);
        if (L < UW && u < HID) {
            float* px = reinterpret_cast<float*>(&x);
            #pragma unroll
            for (int g = 0; g < 4; g++) {
                int c = g * HID + u;
                float s0 = b_ih[c] + b_hh[c];
                #pragma unroll
                for (int e = 0; e < EMBED; e++)
                    s0 += emb[v * EMBED + e] * W_ih[c * EMBED + e];
                px[g] = (g == 2) ? s0 : 0.5f * s0;
            }
        }
        gX2[i] = x;
    }

    for (int u = tid; u < HID; u += blockDim.x) {
        float s = 0.f;
        for (int m = 0; m < HID; m++) s += W2[m] * W1[m * HID + u];
        gq[u] = s;
    }
    if (tid == 0) {
        float s = b2[0];
        for (int m = 0; m < HID; m++) s += W2[m] * b1[m];
        gc0 = s;
    }
}

// ---------------------------------------------------------------------------
__device__ __forceinline__ ull ffma2(ull a, ull b, ull c) {
    ull d;
    asm("fma.rn.f32x2 %0, %1, %2, %3;" : "=l"(d) : "l"(a), "l"(b), "l"(c));
    return d;
}
__device__ __forceinline__ ull dup_(float x) {
    ull d;
    asm("mov.b64 %0, {%1, %1};" : "=l"(d) : "f"(x));
    return d;
}
__device__ __forceinline__ float lo_(ull v) { return __uint_as_float((unsigned)v); }
__device__ __forceinline__ float hi_(ull v) { return __uint_as_float((unsigned)(v >> 32)); }

__device__ __forceinline__ float tanhfast(float x) {
    float y;
    asm("tanh.approx.f32 %0, %1;" : "=f"(y) : "f"(x));
    return y;
}
// gate pre-scaled by 0.5: sigma(2y) = 0.5*tanh(y)+0.5
__device__ __forceinline__ float sigp(float y) { return fmaf(0.5f, tanhfast(y), 0.5f); }

// 4 k's of FFMA2 for all rows (weight ull pairs Wn = (if),(go); h-dups per row)
#define K4(W0a, W0b, W1a, W1b, W2a, W2b, W3a, W3b)                             \
    _Pragma("unroll")                                                          \
    for (int j = 0; j < ROWS; j++) {                                           \
        aif[j] = ffma2(W0a, hA[j], aif[j]);  ago[j] = ffma2(W0b, hA[j], ago[j]); \
        aif[j] = ffma2(W1a, hB[j], aif[j]);  ago[j] = ffma2(W1b, hB[j], ago[j]); \
        aif[j] = ffma2(W2a, hC[j], aif[j]);  ago[j] = ffma2(W2b, hC[j], ago[j]); \
        aif[j] = ffma2(W3a, hD[j], aif[j]);  ago[j] = ffma2(W3b, hD[j], ago[j]); \
    }

// ---------------------------------------------------------------------------
// CTA = 2 warps, 4 batch rows. UNIT-SPLIT: warp w computes gates for units
// [25w, 25w+25) over the FULL k-sum (no partial exchange). Each warp streams
// only its half of the weight table (1 LDG.128 per k). h is shared via
// double-buffered SMEM: read sH[p], write sH[1-p], ONE __syncthreads per step.
// Lane L owns unit u = 25w + L (lanes 25-31 compute dead lanes, never stored).
// ---------------------------------------------------------------------------
__global__ __launch_bounds__(64) void lstm_kernel(const int* __restrict__ tokens,
                                                  float* __restrict__ out)
{
    __shared__ __align__(16) float sH[2][ROWS][SROWF];

    const int lane = threadIdx.x & 31;
    const int wrp  = threadIdx.x >> 5;
    const int b0   = blockIdx.x * ROWS;
    const int base = wrp * 32 + lane;            // table slot
    const int u    = wrp * UW + lane;            // owned unit (live if lane<UW)
    const bool uok = (lane < UW);

    for (int i = threadIdx.x; i < 2 * ROWS * SROWF; i += 64)
        (&sH[0][0][0])[i] = 0.f;
    __syncthreads();

    float c[ROWS], h[ROWS];
    #pragma unroll
    for (int j = 0; j < ROWS; j++) { c[j] = 0.f; h[j] = 0.f; }

    // register-cached weights for k = 0..KC-1 (this warp's unit half)
    ull cw[KC * 2];
    #pragma unroll
    for (int k = 0; k < KC; k++) {
        ulonglong2 v = __ldg(reinterpret_cast<const ulonglong2*>(gW2 + k * 64 + base));
        cw[2 * k]     = v.x;    // (0.5Wi, 0.5Wf)
        cw[2 * k + 1] = v.y;    // (Wg, 0.5Wo)
    }

    const float4* __restrict__ Wp = gW2;
    const float4* __restrict__ Xp = gX2;

    const int* tp[ROWS];
    int tk[ROWS];
    #pragma unroll
    for (int j = 0; j < ROWS; j++) {
        tp[j] = tokens + (size_t)(b0 + j) * TLEN;
        tk[j] = __ldg(tp[j]);
    }

    for (int t = 0; t < TLEN; ++t) {
        const int p = t & 1;
        const int t2 = (t + 1 < TLEN) ? t + 1 : t;
        int tkn[ROWS];
        #pragma unroll
        for (int j = 0; j < ROWS; j++) tkn[j] = __ldg(tp[j] + t2);

        // accumulators: (i,f) and (g,o) packs, init from token gate-init table
        ull aif[ROWS], ago[ROWS];
        #pragma unroll
        for (int j = 0; j < ROWS; j++) {
            ulonglong2 v = __ldg(reinterpret_cast<const ulonglong2*>(Xp + tk[j] * 64 + base));
            aif[j] = v.x;  ago[j] = v.y;
        }

        // ---- cached k's (0..KC-1), groups of 4
        #pragma unroll
        for (int kg = 0; kg < KC; kg += 4) {
            ull hA[ROWS], hB[ROWS], hC[ROWS], hD[ROWS];
            #pragma unroll
            for (int j = 0; j < ROWS; j++) {
                float4 hv = *reinterpret_cast<const float4*>(&sH[p][j][kg]);
                hA[j] = dup_(hv.x);  hB[j] = dup_(hv.y);
                hC[j] = dup_(hv.z);  hD[j] = dup_(hv.w);
            }
            K4(cw[2*kg+0], cw[2*kg+1], cw[2*kg+2], cw[2*kg+3],
               cw[2*kg+4], cw[2*kg+5], cw[2*kg+6], cw[2*kg+7])
        }

        // ---- streamed k's (KC..47), groups of 4: one LDG.128 per k
        #pragma unroll
        for (int kg = KC; kg < 48; kg += 4) {
            ulonglong2 w0 = __ldg(reinterpret_cast<const ulonglong2*>(Wp + (kg + 0) * 64 + base));
            ulonglong2 w1 = __ldg(reinterpret_cast<const ulonglong2*>(Wp + (kg + 1) * 64 + base));
            ulonglong2 w2 = __ldg(reinterpret_cast<const ulonglong2*>(Wp + (kg + 2) * 64 + base));
            ulonglong2 w3 = __ldg(reinterpret_cast<const ulonglong2*>(Wp + (kg + 3) * 64 + base));
            ull hA[ROWS], hB[ROWS], hC[ROWS], hD[ROWS];
            #pragma unroll
            for (int j = 0; j < ROWS; j++) {
                float4 hv = *reinterpret_cast<const float4*>(&sH[p][j][kg]);
                hA[j] = dup_(hv.x);  hB[j] = dup_(hv.y);
                hC[j] = dup_(hv.z);  hD[j] = dup_(hv.w);
            }
            K4(w0.x, w0.y, w1.x, w1.y, w2.x, w2.y, w3.x, w3.y)
        }

        // ---- final pair k = 48, 49
        {
            ulonglong2 w0 = __ldg(reinterpret_cast<const ulonglong2*>(Wp + 48 * 64 + base));
            ulonglong2 w1 = __ldg(reinterpret_cast<const ulonglong2*>(Wp + 49 * 64 + base));
            #pragma unroll
            for (int j = 0; j < ROWS; j++) {
                float2 hv = *reinterpret_cast<const float2*>(&sH[p][j][48]);
                ull hA = dup_(hv.x), hB = dup_(hv.y);
                aif[j] = ffma2(w0.x, hA, aif[j]);  ago[j] = ffma2(w0.y, hA, ago[j]);
                aif[j] = ffma2(w1.x, hB, aif[j]);  ago[j] = ffma2(w1.y, hB, ago[j]);
            }
        }

        // ---- epilogue: one unit per lane, 4 rows; forward old h on pad tokens
        #pragma unroll
        for (int j = 0; j < ROWS; j++) {
            float i = sigp(lo_(aif[j]));
            float f = sigp(hi_(aif[j]));
            float g = tanhfast(lo_(ago[j]));
            float o = sigp(hi_(ago[j]));
            float cn = fmaf(f, c[j], i * g);
            float hn = o * tanhfast(cn);
            if (tk[j] != 0) { c[j] = cn; h[j] = hn; }
            if (uok) sH[1 - p][j][u] = h[j];     // unconditional state forward
        }
        __syncthreads();                          // one barrier per step

        #pragma unroll
        for (int j = 0; j < ROWS; j++) tk[j] = tkn[j];
    }

    // collapsed MLP head: out = sigmoid(c0 + q . h_final); final h in sH[0]
    if (wrp == 0 && lane < ROWS) {
        const int j = lane;
        float s = gc0;
        #pragma unroll 10
        for (int k = 0; k < HID; k++) s += gq[k] * sH[0][j][k];
        out[b0 + j] = 1.0f / (1.0f + __expf(-s));
    }
}

// ---------------------------------------------------------------------------
extern "C" void kernel_launch(void* const* d_in, const int* in_sizes, int n_in,
                              void* d_out, int out_size)
{
    const int*   tokens = (const int*)  d_in[0];
    const float* emb    = (const float*)d_in[1];
    const float* W_ih   = (const float*)d_in[2];
    const float* W_hh   = (const float*)d_in[3];
    const float* b_ih   = (const float*)d_in[4];
    const float* b_hh   = (const float*)d_in[5];
    const float* W1     = (const float*)d_in[6];
    const float* b1     = (const float*)d_in[7];
    const float* W2     = (const float*)d_in[8];
    const float* b2     = (const float*)d_in[9];
    float* out = (float*)d_out;

    prep_kernel<<<1, 256>>>(emb, W_ih, W_hh, b_ih, b_hh, W1, b1, W2, b2);
    lstm_kernel<<<NBATCH / ROWS, 64>>>(tokens, out);
}

// round 11
// speedup vs baseline: 1.5861x; 1.0965x over previous
#include <cuda_runtime.h>
#include <cstdint>

#define VOCAB 14
#define EMBED 10
#define HID   50
#define UW    25          // units per warp
#define KC    16          // k's cached in registers (64 regs)
#define SROWF 52          // sH row stride in floats
#define TLEN  2048
#define NBATCH 4096
#define ROWS  2           // batch rows per CTA (shared by both warps)

typedef unsigned long long ull;

// gW2[k*64 + w*32 + lane] = (0.5*Wi, 0.5*Wf, Wg, 0.5*Wo) for unit u = w*25+lane (lane<25; else 0)
// gX2[v*64 + w*32 + lane] = per-token gate init for unit u, same scaling
__device__ float4 gW2[HID * 64];
__device__ float4 gX2[VOCAB * 64];
__device__ float  gq[HID];
__device__ float  gc0;

// ---------------------------------------------------------------------------
__global__ void prep_kernel(const float* __restrict__ emb,
                            const float* __restrict__ W_ih,
                            const float* __restrict__ W_hh,
                            const float* __restrict__ b_ih,
                            const float* __restrict__ b_hh,
                            const float* __restrict__ W1,
                            const float* __restrict__ b1,
                            const float* __restrict__ W2,
                            const float* __restrict__ b2)
{
    int tid = threadIdx.x;

    for (int i = tid; i < HID * 64; i += blockDim.x) {
        int k = i / 64, s = i % 64;
        int w = s >> 5, L = s & 31;
        int u = w * UW + L;
        float4 v = make_float4(0.f, 0.f, 0.f, 0.f);
        if (L < UW && u < HID) {
            v.x = 0.5f * W_hh[(0 * HID + u) * HID + k];
            v.y = 0.5f * W_hh[(1 * HID + u) * HID + k];
            v.z =        W_hh[(2 * HID + u) * HID + k];
            v.w = 0.5f * W_hh[(3 * HID + u) * HID + k];
        }
        gW2[i] = v;
    }

    for (int i = tid; i < VOCAB * 64; i += blockDim.x) {
        int v = i / 64, s = i % 64;
        int w = s >> 5, L = s & 31;
        int u = w * UW + L;
        float4 x = make_float4(0.f, 0.f, 0.f, 0.f);
        if (L < UW && u < HID) {
            float* px = reinterpret_cast<float*>(&x);
            #pragma unroll
            for (int g = 0; g < 4; g++) {
                int c = g * HID + u;
                float s0 = b_ih[c] + b_hh[c];
                #pragma unroll
                for (int e = 0; e < EMBED; e++)
                    s0 += emb[v * EMBED + e] * W_ih[c * EMBED + e];
                px[g] = (g == 2) ? s0 : 0.5f * s0;
            }
        }
        gX2[i] = x;
    }

    for (int u = tid; u < HID; u += blockDim.x) {
        float s = 0.f;
        for (int m = 0; m < HID; m++) s += W2[m] * W1[m * HID + u];
        gq[u] = s;
    }
    if (tid == 0) {
        float s = b2[0];
        for (int m = 0; m < HID; m++) s += W2[m] * b1[m];
        gc0 = s;
    }
}

// ---------------------------------------------------------------------------
__device__ __forceinline__ ull ffma2(ull a, ull b, ull c) {
    ull d;
    asm("fma.rn.f32x2 %0, %1, %2, %3;" : "=l"(d) : "l"(a), "l"(b), "l"(c));
    return d;
}
__device__ __forceinline__ ull dup_(float x) {
    ull d;
    asm("mov.b64 %0, {%1, %1};" : "=l"(d) : "f"(x));
    return d;
}
__device__ __forceinline__ float lo_(ull v) { return __uint_as_float((unsigned)v); }
__device__ __forceinline__ float hi_(ull v) { return __uint_as_float((unsigned)(v >> 32)); }

__device__ __forceinline__ float tanhfast(float x) {
    float y;
    asm("tanh.approx.f32 %0, %1;" : "=f"(y) : "f"(x));
    return y;
}
// gate pre-scaled by 0.5: sigma(2y) = 0.5*tanh(y)+0.5
__device__ __forceinline__ float sigp(float y) { return fmaf(0.5f, tanhfast(y), 0.5f); }

// 4 k's of FFMA2 for all rows (weight ull pairs Wn = (if),(go); h-dups per row)
#define K4(W0a, W0b, W1a, W1b, W2a, W2b, W3a, W3b)                             \
    _Pragma("unroll")                                                          \
    for (int j = 0; j < ROWS; j++) {                                           \
        aif[j] = ffma2(W0a, hA[j], aif[j]);  ago[j] = ffma2(W0b, hA[j], ago[j]); \
        aif[j] = ffma2(W1a, hB[j], aif[j]);  ago[j] = ffma2(W1b, hB[j], ago[j]); \
        aif[j] = ffma2(W2a, hC[j], aif[j]);  ago[j] = ffma2(W2b, hC[j], ago[j]); \
        aif[j] = ffma2(W3a, hD[j], aif[j]);  ago[j] = ffma2(W3b, hD[j], ago[j]); \
    }

// ---------------------------------------------------------------------------
// CTA = 2 warps, 2 batch rows. UNIT-SPLIT: warp w computes gates for units
// [25w, 25w+25) over the FULL k-sum; each warp streams only its half of the
// weight table (1 LDG.128 per k). h shared via double-buffered SMEM, ONE
// __syncthreads per step. 2048 CTAs -> ~6.9 warps/SMSP for latency hiding.
// ---------------------------------------------------------------------------
__global__ __launch_bounds__(64) void lstm_kernel(const int* __restrict__ tokens,
                                                  float* __restrict__ out)
{
    __shared__ __align__(16) float sH[2][ROWS][SROWF];

    const int lane = threadIdx.x & 31;
    const int wrp  = threadIdx.x >> 5;
    const int b0   = blockIdx.x * ROWS;
    const int base = wrp * 32 + lane;            // table slot
    const int u    = wrp * UW + lane;            // owned unit (live if lane<UW)
    const bool uok = (lane < UW);

    for (int i = threadIdx.x; i < 2 * ROWS * SROWF; i += 64)
        (&sH[0][0][0])[i] = 0.f;
    __syncthreads();

    float c[ROWS], h[ROWS];
    #pragma unroll
    for (int j = 0; j < ROWS; j++) { c[j] = 0.f; h[j] = 0.f; }

    // register-cached weights for k = 0..KC-1 (this warp's unit half)
    ull cw[KC * 2];
    #pragma unroll
    for (int k = 0; k < KC; k++) {
        ulonglong2 v = __ldg(reinterpret_cast<const ulonglong2*>(gW2 + k * 64 + base));
        cw[2 * k]     = v.x;    // (0.5Wi, 0.5Wf)
        cw[2 * k + 1] = v.y;    // (Wg, 0.5Wo)
    }

    const float4* __restrict__ Wp = gW2;
    const float4* __restrict__ Xp = gX2;

    const int* tp[ROWS];
    int tk[ROWS];
    #pragma unroll
    for (int j = 0; j < ROWS; j++) {
        tp[j] = tokens + (size_t)(b0 + j) * TLEN;
        tk[j] = __ldg(tp[j]);
    }

    for (int t = 0; t < TLEN; ++t) {
        const int p = t & 1;
        const int t2 = (t + 1 < TLEN) ? t + 1 : t;
        int tkn[ROWS];
        #pragma unroll
        for (int j = 0; j < ROWS; j++) tkn[j] = __ldg(tp[j] + t2);

        // accumulators: (i,f) and (g,o) packs, init from token gate-init table
        ull aif[ROWS], ago[ROWS];
        #pragma unroll
        for (int j = 0; j < ROWS; j++) {
            ulonglong2 v = __ldg(reinterpret_cast<const ulonglong2*>(Xp + tk[j] * 64 + base));
            aif[j] = v.x;  ago[j] = v.y;
        }

        // ---- cached k's (0..KC-1), groups of 4
        #pragma unroll
        for (int kg = 0; kg < KC; kg += 4) {
            ull hA[ROWS], hB[ROWS], hC[ROWS], hD[ROWS];
            #pragma unroll
            for (int j = 0; j < ROWS; j++) {
                float4 hv = *reinterpret_cast<const float4*>(&sH[p][j][kg]);
                hA[j] = dup_(hv.x);  hB[j] = dup_(hv.y);
                hC[j] = dup_(hv.z);  hD[j] = dup_(hv.w);
            }
            K4(cw[2*kg+0], cw[2*kg+1], cw[2*kg+2], cw[2*kg+3],
               cw[2*kg+4], cw[2*kg+5], cw[2*kg+6], cw[2*kg+7])
        }

        // ---- streamed k's (KC..47), groups of 4: one LDG.128 per k
        #pragma unroll
        for (int kg = KC; kg < 48; kg += 4) {
            ulonglong2 w0 = __ldg(reinterpret_cast<const ulonglong2*>(Wp + (kg + 0) * 64 + base));
            ulonglong2 w1 = __ldg(reinterpret_cast<const ulonglong2*>(Wp + (kg + 1) * 64 + base));
            ulonglong2 w2 = __ldg(reinterpret_cast<const ulonglong2*>(Wp + (kg + 2) * 64 + base));
            ulonglong2 w3 = __ldg(reinterpret_cast<const ulonglong2*>(Wp + (kg + 3) * 64 + base));
            ull hA[ROWS], hB[ROWS], hC[ROWS], hD[ROWS];
            #pragma unroll
            for (int j = 0; j < ROWS; j++) {
                float4 hv = *reinterpret_cast<const float4*>(&sH[p][j][kg]);
                hA[j] = dup_(hv.x);  hB[j] = dup_(hv.y);
                hC[j] = dup_(hv.z);  hD[j] = dup_(hv.w);
            }
            K4(w0.x, w0.y, w1.x, w1.y, w2.x, w2.y, w3.x, w3.y)
        }

        // ---- final pair k = 48, 49
        {
            ulonglong2 w0 = __ldg(reinterpret_cast<const ulonglong2*>(Wp + 48 * 64 + base));
            ulonglong2 w1 = __ldg(reinterpret_cast<const ulonglong2*>(Wp + 49 * 64 + base));
            #pragma unroll
            for (int j = 0; j < ROWS; j++) {
                float2 hv = *reinterpret_cast<const float2*>(&sH[p][j][48]);
                ull hA = dup_(hv.x), hB = dup_(hv.y);
                aif[j] = ffma2(w0.x, hA, aif[j]);  ago[j] = ffma2(w0.y, hA, ago[j]);
                aif[j] = ffma2(w1.x, hB, aif[j]);  ago[j] = ffma2(w1.y, hB, ago[j]);
            }
        }

        // ---- epilogue: one unit per lane; forward old h on pad tokens
        #pragma unroll
        for (int j = 0; j < ROWS; j++) {
            float i = sigp(lo_(aif[j]));
            float f = sigp(hi_(aif[j]));
            float g = tanhfast(lo_(ago[j]));
            float o = sigp(hi_(ago[j]));
            float cn = fmaf(f, c[j], i * g);
            float hn = o * tanhfast(cn);
            if (tk[j] != 0) { c[j] = cn; h[j] = hn; }
            if (uok) sH[1 - p][j][u] = h[j];     // unconditional state forward
        }
        __syncthreads();                          // one barrier per step

        #pragma unroll
        for (int j = 0; j < ROWS; j++) tk[j] = tkn[j];
    }

    // collapsed MLP head: out = sigmoid(c0 + q . h_final); final h in sH[0]
    if (wrp == 0 && lane < ROWS) {
        const int j = lane;
        float s = gc0;
        #pragma unroll 10
        for (int k = 0; k < HID; k++) s += gq[k] * sH[0][j][k];
        out[b0 + j] = 1.0f / (1.0f + __expf(-s));
    }
}

// ---------------------------------------------------------------------------
extern "C" void kernel_launch(void* const* d_in, const int* in_sizes, int n_in,
                              void* d_out, int out_size)
{
    const int*   tokens = (const int*)  d_in[0];
    const float* emb    = (const float*)d_in[1];
    const float* W_ih   = (const float*)d_in[2];
    const float* W_hh   = (const float*)d_in[3];
    const float* b_ih   = (const float*)d_in[4];
    const float* b_hh   = (const float*)d_in[5];
    const float* W1     = (const float*)d_in[6];
    const float* b1     = (const float*)d_in[7];
    const float* W2     = (const float*)d_in[8];
    const float* b2     = (const float*)d_in[9];
    float* out = (float*)d_out;

    prep_kernel<<<1, 256>>>(emb, W_ih, W_hh, b_ih, b_hh, W1, b1, W2, b2);
    lstm_kernel<<<NBATCH / ROWS, 64>>>(tokens, out);
}